// round 1
// baseline (speedup 1.0000x reference)
#include <cuda_runtime.h>

#define NN 100000
#define NE 600000

// ---------------- scratch (device globals; no allocation allowed) ----------
__device__ float    g_bufH[(size_t)NN * 128];
__device__ float    g_bufA[(size_t)NN * 128];
__device__ float    g_bufB[(size_t)NN * 128];
__device__ float    g_dinv[NN];
__device__ float    g_norm[NE];
__device__ unsigned g_x0[32];
__device__ unsigned g_x1[32];

// ---------------- degree / norm precompute --------------------------------
__global__ void k_init() {
    int i = blockIdx.x * blockDim.x + threadIdx.x;
    if (i < NN) g_dinv[i] = 1.0f;        // self-loop weight 1
    if (i < 32) { g_x0[i] = 0u; g_x1[i] = 0u; }
}

__global__ void k_deg(const int* __restrict__ dst, const float* __restrict__ ew) {
    int e = blockIdx.x * blockDim.x + threadIdx.x;
    if (e < NE) atomicAdd(&g_dinv[dst[e]], ew[e]);
}

__global__ void k_rsqrt() {
    int i = blockIdx.x * blockDim.x + threadIdx.x;
    if (i < NN) g_dinv[i] = rsqrtf(g_dinv[i]);
}

__global__ void k_norm(const int* __restrict__ src, const int* __restrict__ dst,
                       const float* __restrict__ ew) {
    int e = blockIdx.x * blockDim.x + threadIdx.x;
    if (e < NE) g_norm[e] = g_dinv[src[e]] * ew[e] * g_dinv[dst[e]];
}

// ---------------- dense GEMM: H[NN,OUT] = relu?(X[NN,IN]) @ W[IN,OUT] ------
template <int IN, int OUT, bool RELU_IN>
__global__ void k_gemm(const float* __restrict__ X, const float* __restrict__ W,
                       float* __restrict__ H) {
    constexpr int P  = OUT / 32;               // outputs per thread
    constexpr int KT = (IN < 64) ? IN : 64;    // k-tile (smem <= 32KB)
    __shared__ float sW[KT * OUT];

    int row = blockIdx.x * 8 + threadIdx.y;
    int tid = threadIdx.y * 32 + threadIdx.x;

    float acc[P];
#pragma unroll
    for (int j = 0; j < P; j++) acc[j] = 0.0f;

    for (int k0 = 0; k0 < IN; k0 += KT) {
        for (int i = tid; i < KT * OUT; i += 256) sW[i] = W[k0 * OUT + i];
        __syncthreads();
        if (row < NN) {
#pragma unroll
            for (int k = 0; k < KT; k++) {
                float xv = X[(size_t)row * IN + k0 + k];
                if (RELU_IN) xv = fmaxf(xv, 0.0f);
#pragma unroll
                for (int j = 0; j < P; j++)
                    acc[j] += xv * sW[k * OUT + threadIdx.x * P + j];
            }
        }
        __syncthreads();
    }
    if (row < NN) {
#pragma unroll
        for (int j = 0; j < P; j++)
            H[(size_t)row * OUT + threadIdx.x * P + j] = acc[j];
    }
}

// ---------------- agg init: agg = h * dinv^2 + b ---------------------------
template <int OUT>
__global__ void k_selfbias(const float* __restrict__ h, const float* __restrict__ b,
                           float* __restrict__ agg) {
    constexpr int G = OUT / 4;
    int idx = blockIdx.x * blockDim.x + threadIdx.x;
    if (idx < NN * G) {
        int i = idx / G, g = idx - i * G;
        float d = g_dinv[i]; d *= d;
        float4 hv = ((const float4*)h)[idx];
        float4 bv = ((const float4*)b)[g];
        float4 o;
        o.x = hv.x * d + bv.x;
        o.y = hv.y * d + bv.y;
        o.z = hv.z * d + bv.z;
        o.w = hv.w * d + bv.w;
        ((float4*)agg)[idx] = o;
    }
}

// ---------------- edge scatter: agg[dst] += norm * h[src] ------------------
template <int OUT>
__global__ void k_scatter(const int* __restrict__ src, const int* __restrict__ dst,
                          const float* __restrict__ h, float* __restrict__ agg) {
    constexpr int G = OUT / 4;
    int idx = blockIdx.x * blockDim.x + threadIdx.x;
    if (idx < NE * G) {
        int e = idx / G, g = idx - e * G;
        float n = g_norm[e];
        int s = src[e], d = dst[e];
        float4 hv = ((const float4*)(h + (size_t)s * OUT))[g];
        float* p = agg + (size_t)d * OUT + g * 4;
        atomicAdd(p + 0, n * hv.x);
        atomicAdd(p + 1, n * hv.y);
        atomicAdd(p + 2, n * hv.z);
        atomicAdd(p + 3, n * hv.w);
    }
}

// ---------------- global max over relu(buf), 32 features -------------------
__global__ void k_segmax32(const float* __restrict__ buf, unsigned* __restrict__ out) {
    int f = threadIdx.x & 31;
    int w = threadIdx.x >> 5;
    float m = 0.0f;
    for (int i = blockIdx.x * 8 + w; i < NN; i += gridDim.x * 8)
        m = fmaxf(m, buf[(size_t)i * 32 + f]);   // relu folded: m starts at 0
    __shared__ float s[256];
    s[threadIdx.x] = m;
    __syncthreads();
    if (threadIdx.x < 32) {
#pragma unroll
        for (int ww = 1; ww < 8; ww++) m = fmaxf(m, s[ww * 32 + f]);
        atomicMax(&out[f], __float_as_uint(m));  // m >= 0 -> uint order == float order
    }
}

// ---------------- MLP head + softmax + code write --------------------------
__global__ void k_head(const float* __restrict__ C2ER,
                       const unsigned* __restrict__ x0, const unsigned* __restrict__ x1,
                       const float* __restrict__ L1W, const float* __restrict__ L1b,
                       const float* __restrict__ L2W, const float* __restrict__ L2b,
                       const float* __restrict__ L3W, const float* __restrict__ L3b,
                       float* __restrict__ out) {
    __shared__ float code[68], z1[128], z2[128], logits[10];
    int t = threadIdx.x;
    if (t < 32)       code[t] = __uint_as_float(x0[t]);
    else if (t < 64)  code[t] = __uint_as_float(x1[t - 32]);
    else if (t < 68)  code[t] = C2ER[t - 64];
    __syncthreads();

    float a = L1b[t];
#pragma unroll
    for (int i = 0; i < 68; i++) a += code[i] * L1W[i * 128 + t];
    z1[t] = fmaxf(a, 0.0f);
    __syncthreads();

    a = L2b[t];
#pragma unroll
    for (int i = 0; i < 128; i++) a += z1[i] * L2W[i * 128 + t];
    z2[t] = fmaxf(a, 0.0f);
    __syncthreads();

    if (t < 10) {
        float s = L3b[t];
#pragma unroll
        for (int i = 0; i < 128; i++) s += z2[i] * L3W[i * 10 + t];
        logits[t] = s;
    }
    __syncthreads();

    if (t == 0) {
        float mx = -1e30f;
        for (int j = 0; j < 10; j++) mx = fmaxf(mx, logits[j]);
        float e[10], sum = 0.0f;
        for (int j = 0; j < 10; j++) { e[j] = expf(logits[j] - mx); sum += e[j]; }
        float inv = 1.0f / sum;
        for (int j = 0; j < 10; j++) out[j] = e[j] * inv;
        for (int j = 0; j < 68; j++) out[10 + j] = code[j];
    }
}

// ---------------- launch ----------------------------------------------------
extern "C" void kernel_launch(void* const* d_in, const int* in_sizes, int n_in,
                              void* d_out, int out_size) {
    const float* x    = (const float*)d_in[0];
    const int*   ei   = (const int*)d_in[1];
    const float* ew   = (const float*)d_in[2];
    const float* C2ER = (const float*)d_in[4];
    const float* W1 = (const float*)d_in[5],  *b1 = (const float*)d_in[6];
    const float* W2 = (const float*)d_in[7],  *b2 = (const float*)d_in[8];
    const float* W3 = (const float*)d_in[9],  *b3 = (const float*)d_in[10];
    const float* W4 = (const float*)d_in[11], *b4 = (const float*)d_in[12];
    const float* L1W = (const float*)d_in[13], *L1b = (const float*)d_in[14];
    const float* L2W = (const float*)d_in[15], *L2b = (const float*)d_in[16];
    const float* L3W = (const float*)d_in[17], *L3b = (const float*)d_in[18];
    float* out = (float*)d_out;

    const int* src = ei;
    const int* dst = ei + NE;

    void *pH, *pA, *pB, *px0, *px1;
    cudaGetSymbolAddress(&pH, g_bufH);
    cudaGetSymbolAddress(&pA, g_bufA);
    cudaGetSymbolAddress(&pB, g_bufB);
    cudaGetSymbolAddress(&px0, g_x0);
    cudaGetSymbolAddress(&px1, g_x1);
    float* H = (float*)pH;
    float* A = (float*)pA;
    float* B = (float*)pB;

    dim3 gblk(32, 8);
    const int GG = (NN + 7) / 8;   // 12500 blocks for GEMM

    k_init  <<<(NN + 255) / 256, 256>>>();
    k_deg   <<<(NE + 255) / 256, 256>>>(dst, ew);
    k_rsqrt <<<(NN + 255) / 256, 256>>>();
    k_norm  <<<(NE + 255) / 256, 256>>>(src, dst, ew);

    // Layer 1: x(8) -> A(32)
    k_gemm<8, 32, false><<<GG, gblk>>>(x, W1, H);
    k_selfbias<32><<<(NN * 8 + 255) / 256, 256>>>(H, b1, A);
    k_scatter<32><<<(NE * 8 + 255) / 256, 256>>>(src, dst, H, A);
    k_segmax32<<<448, 256>>>(A, (unsigned*)px0);

    // Layer 2: relu(A)(32) -> B(128)
    k_gemm<32, 128, true><<<GG, gblk>>>(A, W2, H);
    k_selfbias<128><<<(NN * 32 + 255) / 256, 256>>>(H, b2, B);
    k_scatter<128><<<(NE * 32 + 255) / 256, 256>>>(src, dst, H, B);

    // Layer 3: relu(B)(128) -> A(128)
    k_gemm<128, 128, true><<<GG, gblk>>>(B, W3, H);
    k_selfbias<128><<<(NN * 32 + 255) / 256, 256>>>(H, b3, A);
    k_scatter<128><<<(NE * 32 + 255) / 256, 256>>>(src, dst, H, A);

    // Layer 4: relu(A)(128) -> B(32)
    k_gemm<128, 32, true><<<GG, gblk>>>(A, W4, H);
    k_selfbias<32><<<(NN * 8 + 255) / 256, 256>>>(H, b4, B);
    k_scatter<32><<<(NE * 8 + 255) / 256, 256>>>(src, dst, H, B);
    k_segmax32<<<448, 256>>>(B, (unsigned*)px1);

    // Head
    k_head<<<1, 128>>>(C2ER, (const unsigned*)px0, (const unsigned*)px1,
                       L1W, L1b, L2W, L2b, L3W, L3b, out);
}

// round 2
// speedup vs baseline: 2.6252x; 2.6252x over previous
#include <cuda_runtime.h>

#define NN 100000
#define NE 600000
#define NBLK 196   // ceil(NN/512) scan blocks

// ---------------- scratch (device globals; no allocation allowed) ----------
__device__ float    g_bufH[(size_t)NN * 128];
__device__ float    g_bufA[(size_t)NN * 128];
__device__ float    g_bufB[(size_t)NN * 128];
__device__ float    g_dinv[NN];
__device__ int      g_cnt[NN];
__device__ int      g_loc[NN];
__device__ int      g_bsum[NBLK];
__device__ int      g_rowptr[NN + 1];
__device__ int      g_cur[NN];
__device__ int      g_esrc[NE];
__device__ float    g_enorm[NE];
__device__ unsigned g_x0[32];
__device__ unsigned g_x1[32];

// ---------------- init: dinv=1 (self loop), cnt=0, segmax accumulators -----
__global__ void k_init() {
    int i = blockIdx.x * blockDim.x + threadIdx.x;
    if (i < NN) { g_dinv[i] = 1.0f; g_cnt[i] = 0; }
    if (i < 32) { g_x0[i] = 0u; g_x1[i] = 0u; }
}

// ---------------- weighted degree + count degree ---------------------------
__global__ void k_deg(const int* __restrict__ dst, const float* __restrict__ ew) {
    int e = blockIdx.x * blockDim.x + threadIdx.x;
    if (e < NE) {
        int d = dst[e];
        atomicAdd(&g_dinv[d], ew[e]);
        atomicAdd(&g_cnt[d], 1);
    }
}

__global__ void k_rsqrt() {
    int i = blockIdx.x * blockDim.x + threadIdx.x;
    if (i < NN) g_dinv[i] = rsqrtf(g_dinv[i]);
}

// ---------------- 3-kernel exclusive scan of g_cnt -> g_rowptr -------------
__global__ void k_scan1() {
    __shared__ int s[512];
    int tid = threadIdx.x;
    int i = blockIdx.x * 512 + tid;
    int v = (i < NN) ? g_cnt[i] : 0;
    s[tid] = v;
    __syncthreads();
#pragma unroll
    for (int off = 1; off < 512; off <<= 1) {
        int t = 0;
        if (tid >= off) t = s[tid - off];
        __syncthreads();
        if (tid >= off) s[tid] += t;
        __syncthreads();
    }
    if (i < NN) g_loc[i] = s[tid] - v;      // exclusive
    if (tid == 511) g_bsum[blockIdx.x] = s[511];
}

__global__ void k_scan2() {
    int run = 0;
    for (int j = 0; j < NBLK; j++) { int t = g_bsum[j]; g_bsum[j] = run; run += t; }
    g_rowptr[NN] = NE;
}

__global__ void k_scan3() {
    int i = blockIdx.x * 512 + threadIdx.x;
    if (i < NN) {
        int r = g_loc[i] + g_bsum[blockIdx.x];
        g_rowptr[i] = r;
        g_cur[i] = r;
    }
}

// ---------------- fill CSR: per-edge norm + insert --------------------------
__global__ void k_fill(const int* __restrict__ src, const int* __restrict__ dst,
                       const float* __restrict__ ew) {
    int e = blockIdx.x * blockDim.x + threadIdx.x;
    if (e < NE) {
        int s = src[e], d = dst[e];
        float n = g_dinv[s] * ew[e] * g_dinv[d];
        int pos = atomicAdd(&g_cur[d], 1);
        g_esrc[pos] = s;
        g_enorm[pos] = n;
    }
}

// ---------------- dense GEMM: H[NN,OUT] = relu?(X[NN,IN]) @ W[IN,OUT] ------
// Block 256 threads, W fully resident in smem, 32-row X tiles in smem,
// each thread computes 4 rows x (4*P) cols in registers. P = OUT/32/... :
//   OUT=128 -> P=4 (one float4 of cols), OUT=32 -> P=1 (one scalar col).
template <int IN, int OUT, bool RELU_IN>
__global__ void k_gemm(const float* __restrict__ X, const float* __restrict__ W,
                       float* __restrict__ H) {
    extern __shared__ float sm[];
    float* sW = sm;                 // IN*OUT floats
    float* sX = sm + IN * OUT;      // 32*IN floats
    constexpr int P  = OUT / 32;    // 1 or 4
    constexpr int K4 = IN / 4;
    int tid = threadIdx.x;
    int tx = tid & 31, ty = tid >> 5;

    for (int i = tid; i < IN * OUT / 4; i += 256)
        ((float4*)sW)[i] = ((const float4*)W)[i];
    __syncthreads();

    const int ntiles = NN / 32;     // 3125, exact
    for (int t = blockIdx.x; t < ntiles; t += gridDim.x) {
        size_t rbase = (size_t)t * 32;
        for (int i = tid; i < 32 * K4; i += 256) {
            float4 v = ((const float4*)X)[rbase * K4 + i];
            if (RELU_IN) {
                v.x = fmaxf(v.x, 0.0f); v.y = fmaxf(v.y, 0.0f);
                v.z = fmaxf(v.z, 0.0f); v.w = fmaxf(v.w, 0.0f);
            }
            ((float4*)sX)[i] = v;
        }
        __syncthreads();

        if constexpr (P == 4) {
            float4 acc[4];
#pragma unroll
            for (int rr = 0; rr < 4; rr++) acc[rr] = make_float4(0.f, 0.f, 0.f, 0.f);
#pragma unroll 2
            for (int k4 = 0; k4 < K4; k4++) {
                float4 xr[4];
#pragma unroll
                for (int rr = 0; rr < 4; rr++)
                    xr[rr] = ((float4*)sX)[(ty * 4 + rr) * K4 + k4];
#pragma unroll
                for (int kk = 0; kk < 4; kk++) {
                    float4 wv = ((float4*)sW)[(k4 * 4 + kk) * 32 + tx];
#pragma unroll
                    for (int rr = 0; rr < 4; rr++) {
                        float xv = ((const float*)&xr[rr])[kk];
                        acc[rr].x += xv * wv.x;
                        acc[rr].y += xv * wv.y;
                        acc[rr].z += xv * wv.z;
                        acc[rr].w += xv * wv.w;
                    }
                }
            }
#pragma unroll
            for (int rr = 0; rr < 4; rr++)
                ((float4*)H)[(rbase + ty * 4 + rr) * 32 + tx] = acc[rr];
        } else {
            float acc[4] = {0.f, 0.f, 0.f, 0.f};
#pragma unroll 2
            for (int k4 = 0; k4 < K4; k4++) {
                float4 xr[4];
#pragma unroll
                for (int rr = 0; rr < 4; rr++)
                    xr[rr] = ((float4*)sX)[(ty * 4 + rr) * K4 + k4];
#pragma unroll
                for (int kk = 0; kk < 4; kk++) {
                    float wv = sW[(k4 * 4 + kk) * 32 + tx];
#pragma unroll
                    for (int rr = 0; rr < 4; rr++)
                        acc[rr] += ((const float*)&xr[rr])[kk] * wv;
                }
            }
#pragma unroll
            for (int rr = 0; rr < 4; rr++)
                H[(rbase + ty * 4 + rr) * 32 + tx] = acc[rr];
        }
        __syncthreads();
    }
}

// ---------------- fused aggregation: agg = h*dinv^2 + b + CSR-gather -------
template <int OUT>
__global__ void k_agg(const float* __restrict__ h, const float* __restrict__ b,
                      float* __restrict__ agg) {
    constexpr int G = OUT / 4;            // float4 groups per node (8 or 32)
    constexpr int NPB = 256 / G;          // nodes per block
    int node = blockIdx.x * NPB + threadIdx.x / G;
    int g = threadIdx.x % G;
    if (node >= NN) return;

    int beg = g_rowptr[node];
    int end = g_rowptr[node + 1];
    float d = g_dinv[node]; d = d * d;

    const float4* h4 = (const float4*)h;
    float4 hv = h4[(size_t)node * G + g];
    float4 bv = ((const float4*)b)[g];
    float4 acc;
    acc.x = hv.x * d + bv.x;
    acc.y = hv.y * d + bv.y;
    acc.z = hv.z * d + bv.z;
    acc.w = hv.w * d + bv.w;

    for (int e = beg; e < end; e++) {
        int s   = g_esrc[e];
        float n = g_enorm[e];
        float4 v = h4[(size_t)s * G + g];
        acc.x += n * v.x;
        acc.y += n * v.y;
        acc.z += n * v.z;
        acc.w += n * v.w;
    }
    ((float4*)agg)[(size_t)node * G + g] = acc;
}

// ---------------- global max over relu(buf), 32 features -------------------
__global__ void k_segmax32(const float* __restrict__ buf, unsigned* __restrict__ out) {
    int f = threadIdx.x & 31;
    int w = threadIdx.x >> 5;
    float m = 0.0f;
    for (int i = blockIdx.x * 8 + w; i < NN; i += gridDim.x * 8)
        m = fmaxf(m, buf[(size_t)i * 32 + f]);   // relu folded: m starts at 0
    __shared__ float s[256];
    s[threadIdx.x] = m;
    __syncthreads();
    if (threadIdx.x < 32) {
#pragma unroll
        for (int ww = 1; ww < 8; ww++) m = fmaxf(m, s[ww * 32 + f]);
        atomicMax(&out[f], __float_as_uint(m));  // m >= 0 -> uint order == float order
    }
}

// ---------------- MLP head + softmax + code write --------------------------
__global__ void k_head(const float* __restrict__ C2ER,
                       const unsigned* __restrict__ x0, const unsigned* __restrict__ x1,
                       const float* __restrict__ L1W, const float* __restrict__ L1b,
                       const float* __restrict__ L2W, const float* __restrict__ L2b,
                       const float* __restrict__ L3W, const float* __restrict__ L3b,
                       float* __restrict__ out) {
    __shared__ float code[68], z1[128], z2[128], logits[10];
    int t = threadIdx.x;
    if (t < 32)       code[t] = __uint_as_float(x0[t]);
    else if (t < 64)  code[t] = __uint_as_float(x1[t - 32]);
    else if (t < 68)  code[t] = C2ER[t - 64];
    __syncthreads();

    float a = L1b[t];
#pragma unroll
    for (int i = 0; i < 68; i++) a += code[i] * L1W[i * 128 + t];
    z1[t] = fmaxf(a, 0.0f);
    __syncthreads();

    a = L2b[t];
#pragma unroll
    for (int i = 0; i < 128; i++) a += z1[i] * L2W[i * 128 + t];
    z2[t] = fmaxf(a, 0.0f);
    __syncthreads();

    if (t < 10) {
        float s = L3b[t];
#pragma unroll
        for (int i = 0; i < 128; i++) s += z2[i] * L3W[i * 10 + t];
        logits[t] = s;
    }
    __syncthreads();

    if (t == 0) {
        float mx = -1e30f;
        for (int j = 0; j < 10; j++) mx = fmaxf(mx, logits[j]);
        float e[10], sum = 0.0f;
        for (int j = 0; j < 10; j++) { e[j] = expf(logits[j] - mx); sum += e[j]; }
        float inv = 1.0f / sum;
        for (int j = 0; j < 10; j++) out[j] = e[j] * inv;
        for (int j = 0; j < 68; j++) out[10 + j] = code[j];
    }
}

// ---------------- launch ----------------------------------------------------
extern "C" void kernel_launch(void* const* d_in, const int* in_sizes, int n_in,
                              void* d_out, int out_size) {
    const float* x    = (const float*)d_in[0];
    const int*   ei   = (const int*)d_in[1];
    const float* ew   = (const float*)d_in[2];
    const float* C2ER = (const float*)d_in[4];
    const float* W1 = (const float*)d_in[5],  *b1 = (const float*)d_in[6];
    const float* W2 = (const float*)d_in[7],  *b2 = (const float*)d_in[8];
    const float* W3 = (const float*)d_in[9],  *b3 = (const float*)d_in[10];
    const float* W4 = (const float*)d_in[11], *b4 = (const float*)d_in[12];
    const float* L1W = (const float*)d_in[13], *L1b = (const float*)d_in[14];
    const float* L2W = (const float*)d_in[15], *L2b = (const float*)d_in[16];
    const float* L3W = (const float*)d_in[17], *L3b = (const float*)d_in[18];
    float* out = (float*)d_out;

    const int* src = ei;
    const int* dst = ei + NE;

    void *pH, *pA, *pB, *px0, *px1;
    cudaGetSymbolAddress(&pH, g_bufH);
    cudaGetSymbolAddress(&pA, g_bufA);
    cudaGetSymbolAddress(&pB, g_bufB);
    cudaGetSymbolAddress(&px0, g_x0);
    cudaGetSymbolAddress(&px1, g_x1);
    float* H = (float*)pH;
    float* A = (float*)pA;
    float* B = (float*)pB;

    // raise dynamic smem limit for the 128x128 GEMM (80KB)
    cudaFuncSetAttribute(k_gemm<128, 128, true>,
                         cudaFuncAttributeMaxDynamicSharedMemorySize, 81920);

    // ---- CSR build + normalization ----
    k_init  <<<(NN + 255) / 256, 256>>>();
    k_deg   <<<(NE + 255) / 256, 256>>>(dst, ew);
    k_rsqrt <<<(NN + 255) / 256, 256>>>();
    k_scan1 <<<NBLK, 512>>>();
    k_scan2 <<<1, 1>>>();
    k_scan3 <<<NBLK, 512>>>();
    k_fill  <<<(NE + 255) / 256, 256>>>(src, dst, ew);

    // ---- Layer 1: x(8) -> A(32) ----
    k_gemm<8, 32, false><<<1184, 256, (8 * 32 + 32 * 8) * 4>>>(x, W1, H);
    k_agg<32><<<(NN + 31) / 32, 256>>>(H, b1, A);
    k_segmax32<<<448, 256>>>(A, (unsigned*)px0);

    // ---- Layer 2: relu(A)(32) -> B(128) ----
    k_gemm<32, 128, true><<<1184, 256, (32 * 128 + 32 * 32) * 4>>>(A, W2, H);
    k_agg<128><<<(NN + 7) / 8, 256>>>(H, b2, B);

    // ---- Layer 3: relu(B)(128) -> A(128) ----
    k_gemm<128, 128, true><<<296, 256, 81920>>>(B, W3, H);
    k_agg<128><<<(NN + 7) / 8, 256>>>(H, b3, A);

    // ---- Layer 4: relu(A)(128) -> B(32) ----
    k_gemm<128, 32, true><<<592, 256, (128 * 32 + 32 * 128) * 4>>>(A, W4, H);
    k_agg<32><<<(NN + 31) / 32, 256>>>(H, b4, B);
    k_segmax32<<<448, 256>>>(B, (unsigned*)px1);

    // ---- Head ----
    k_head<<<1, 128>>>(C2ER, (const unsigned*)px0, (const unsigned*)px1,
                       L1W, L1b, L2W, L2b, L3W, L3b, out);
}

// round 3
// speedup vs baseline: 3.2524x; 1.2389x over previous
#include <cuda_runtime.h>

#define NN 100000
#define NE 600000
#define NBLK 196   // ceil(NN/512) scan blocks

// ---------------- scratch (device globals; no allocation allowed) ----------
__device__ float    g_bufH[(size_t)NN * 128];
__device__ float    g_bufA[(size_t)NN * 128];
__device__ float    g_bufB[(size_t)NN * 128];
__device__ float    g_dinv[NN];
__device__ int      g_cnt[NN];
__device__ int      g_loc[NN];
__device__ int      g_bsum[NBLK];
__device__ int      g_rowptr[NN + 1];
__device__ int      g_cur[NN];
__device__ int2     g_edge[NE];          // {src, float-bits(norm)} packed
__device__ unsigned g_x0[32];
__device__ unsigned g_x1[32];

// ---------------- init ------------------------------------------------------
__global__ void k_init() {
    int i = blockIdx.x * blockDim.x + threadIdx.x;
    if (i < NN) { g_dinv[i] = 1.0f; g_cnt[i] = 0; }
    if (i < 32) { g_x0[i] = 0u; g_x1[i] = 0u; }
}

// ---------------- weighted degree + count degree ----------------------------
__global__ void k_deg(const int* __restrict__ dst, const float* __restrict__ ew) {
    int e = blockIdx.x * blockDim.x + threadIdx.x;
    if (e < NE) {
        int d = dst[e];
        atomicAdd(&g_dinv[d], ew[e]);
        atomicAdd(&g_cnt[d], 1);
    }
}

// ---------------- scan pass 1 (also finishes dinv = rsqrt(deg)) -------------
__global__ void k_scan1() {
    __shared__ int s[512];
    int tid = threadIdx.x;
    int i = blockIdx.x * 512 + tid;
    int v = (i < NN) ? g_cnt[i] : 0;
    if (i < NN) g_dinv[i] = rsqrtf(g_dinv[i]);
    s[tid] = v;
    __syncthreads();
#pragma unroll
    for (int off = 1; off < 512; off <<= 1) {
        int t = 0;
        if (tid >= off) t = s[tid - off];
        __syncthreads();
        if (tid >= off) s[tid] += t;
        __syncthreads();
    }
    if (i < NN) g_loc[i] = s[tid] - v;      // exclusive
    if (tid == 511) g_bsum[blockIdx.x] = s[511];
}

// ---------------- scan pass 2 (parallel over block sums) --------------------
__global__ void k_scan2() {
    __shared__ int s[256];
    int t = threadIdx.x;
    int v = (t < NBLK) ? g_bsum[t] : 0;
    s[t] = v;
    __syncthreads();
#pragma unroll
    for (int off = 1; off < 256; off <<= 1) {
        int u = 0;
        if (t >= off) u = s[t - off];
        __syncthreads();
        if (t >= off) s[t] += u;
        __syncthreads();
    }
    if (t < NBLK) g_bsum[t] = s[t] - v;     // exclusive block offsets
    if (t == 0) g_rowptr[NN] = NE;
}

__global__ void k_scan3() {
    int i = blockIdx.x * 512 + threadIdx.x;
    if (i < NN) {
        int r = g_loc[i] + g_bsum[blockIdx.x];
        g_rowptr[i] = r;
        g_cur[i] = r;
    }
}

// ---------------- fill CSR: per-edge norm + packed insert -------------------
__global__ void k_fill(const int* __restrict__ src, const int* __restrict__ dst,
                       const float* __restrict__ ew) {
    int e = blockIdx.x * blockDim.x + threadIdx.x;
    if (e < NE) {
        int s = src[e], d = dst[e];
        float n = g_dinv[s] * ew[e] * g_dinv[d];
        int pos = atomicAdd(&g_cur[d], 1);
        g_edge[pos] = make_int2(s, __float_as_int(n));
    }
}

// ---------------- fused aggregation: out = h*dinv^2 [+ b] + CSR-gather ------
template <int WID, bool BIAS>
__global__ void k_agg(const float* __restrict__ h, const float* __restrict__ b,
                      float* __restrict__ out) {
    constexpr int G = WID / 4;
    int idx = blockIdx.x * 256 + threadIdx.x;
    int node = idx / G, g = idx % G;
    if (node >= NN) return;

    int beg = g_rowptr[node];
    int end = g_rowptr[node + 1];
    float d = g_dinv[node]; d = d * d;

    const float4* h4 = (const float4*)h;
    float4 hv = h4[(size_t)node * G + g];
    float4 acc;
    if (BIAS) {
        float4 bv = ((const float4*)b)[g];
        acc.x = hv.x * d + bv.x; acc.y = hv.y * d + bv.y;
        acc.z = hv.z * d + bv.z; acc.w = hv.w * d + bv.w;
    } else {
        acc.x = hv.x * d; acc.y = hv.y * d;
        acc.z = hv.z * d; acc.w = hv.w * d;
    }

    for (int e = beg; e < end; e++) {
        int2 ed = g_edge[e];
        float n = __int_as_float(ed.y);
        float4 v = h4[(size_t)ed.x * G + g];
        acc.x += n * v.x; acc.y += n * v.y;
        acc.z += n * v.z; acc.w += n * v.w;
    }
    ((float4*)out)[(size_t)node * G + g] = acc;
}

// ---------------- dense GEMM: H = [relu](X @ W [+ b]) -----------------------
// 256 threads, 64-row tiles, thread tile = 8 rows x P cols (P = OUT/32).
// W fully smem-resident; X-tile loads are warp-uniform broadcasts.
template <int IN, int OUT, bool BIAS, bool RELU>
__global__ void __launch_bounds__(256) k_gemm(const float* __restrict__ X,
                                              const float* __restrict__ W,
                                              const float* __restrict__ b,
                                              float* __restrict__ H) {
    constexpr int P  = OUT / 32;
    constexpr int K4 = IN / 4;
    constexpr int ROWS = 64;
    extern __shared__ float sm[];
    float* sW = sm;                 // IN*OUT
    float* sX = sm + IN * OUT;      // ROWS*IN
    int tid = threadIdx.x;
    int tx = tid & 31, ty = tid >> 5;

    for (int i = tid; i < IN * OUT / 4; i += 256)
        ((float4*)sW)[i] = ((const float4*)W)[i];

    float bv[P];
    if (BIAS) {
#pragma unroll
        for (int j = 0; j < P; j++) bv[j] = b[tx * P + j];
    }
    __syncthreads();

    const int ntiles = (NN + ROWS - 1) / ROWS;
    for (int t = blockIdx.x; t < ntiles; t += gridDim.x) {
        int rbase = t * ROWS;
        for (int i = tid; i < ROWS * K4; i += 256) {
            int r = i / K4;
            float4 v = make_float4(0.f, 0.f, 0.f, 0.f);
            if (rbase + r < NN) v = ((const float4*)X)[(size_t)(rbase + r) * K4 + (i % K4)];
            ((float4*)sX)[i] = v;
        }
        __syncthreads();

        float acc[8][P];
#pragma unroll
        for (int rr = 0; rr < 8; rr++)
#pragma unroll
            for (int j = 0; j < P; j++) acc[rr][j] = 0.0f;

#pragma unroll (K4 <= 8 ? K4 : 2)
        for (int k4 = 0; k4 < K4; k4++) {
            float4 xr[8];
#pragma unroll
            for (int rr = 0; rr < 8; rr++)
                xr[rr] = ((float4*)sX)[(ty * 8 + rr) * K4 + k4];   // warp-uniform bcast
#pragma unroll
            for (int kk = 0; kk < 4; kk++) {
                if constexpr (P == 4) {
                    float4 wv = ((float4*)sW)[(k4 * 4 + kk) * 32 + tx];
#pragma unroll
                    for (int rr = 0; rr < 8; rr++) {
                        float xv = ((const float*)&xr[rr])[kk];
                        acc[rr][0] += xv * wv.x;
                        acc[rr][1] += xv * wv.y;
                        acc[rr][2] += xv * wv.z;
                        acc[rr][3] += xv * wv.w;
                    }
                } else {
                    float wv = sW[(k4 * 4 + kk) * 32 + tx];
#pragma unroll
                    for (int rr = 0; rr < 8; rr++)
                        acc[rr][0] += ((const float*)&xr[rr])[kk] * wv;
                }
            }
        }

#pragma unroll
        for (int rr = 0; rr < 8; rr++) {
            int row = rbase + ty * 8 + rr;
            if (row < NN) {
#pragma unroll
                for (int j = 0; j < P; j++) {
                    float v = acc[rr][j];
                    if (BIAS) v += bv[j];
                    if (RELU) v = fmaxf(v, 0.0f);
                    acc[rr][j] = v;
                }
                if constexpr (P == 4) {
                    float4 o = make_float4(acc[rr][0], acc[rr][1], acc[rr][2], acc[rr][3]);
                    ((float4*)H)[(size_t)row * 32 + tx] = o;
                } else {
                    H[(size_t)row * 32 + tx] = acc[rr][0];
                }
            }
        }
        __syncthreads();
    }
}

// ---------------- global max over relu(buf), 32 features --------------------
__global__ void k_segmax32(const float* __restrict__ buf, unsigned* __restrict__ out) {
    int f = threadIdx.x & 31;
    int w = threadIdx.x >> 5;
    float m = 0.0f;
    for (int i = blockIdx.x * 8 + w; i < NN; i += gridDim.x * 8)
        m = fmaxf(m, buf[(size_t)i * 32 + f]);   // relu folded: m starts at 0
    __shared__ float s[256];
    s[threadIdx.x] = m;
    __syncthreads();
    if (threadIdx.x < 32) {
#pragma unroll
        for (int ww = 1; ww < 8; ww++) m = fmaxf(m, s[ww * 32 + f]);
        atomicMax(&out[f], __float_as_uint(m));
    }
}

// ---------------- MLP head + softmax + code write ---------------------------
__global__ void k_head(const float* __restrict__ C2ER,
                       const unsigned* __restrict__ x0, const unsigned* __restrict__ x1,
                       const float* __restrict__ L1W, const float* __restrict__ L1b,
                       const float* __restrict__ L2W, const float* __restrict__ L2b,
                       const float* __restrict__ L3W, const float* __restrict__ L3b,
                       float* __restrict__ out) {
    __shared__ float code[68], z1[128], z2[128], logits[10];
    int t = threadIdx.x;
    if (t < 32)       code[t] = __uint_as_float(x0[t]);
    else if (t < 64)  code[t] = __uint_as_float(x1[t - 32]);
    else if (t < 68)  code[t] = C2ER[t - 64];
    __syncthreads();

    float a = L1b[t];
#pragma unroll
    for (int i = 0; i < 68; i++) a += code[i] * L1W[i * 128 + t];
    z1[t] = fmaxf(a, 0.0f);
    __syncthreads();

    a = L2b[t];
#pragma unroll
    for (int i = 0; i < 128; i++) a += z1[i] * L2W[i * 128 + t];
    z2[t] = fmaxf(a, 0.0f);
    __syncthreads();

    if (t < 10) {
        float s = L3b[t];
#pragma unroll
        for (int i = 0; i < 128; i++) s += z2[i] * L3W[i * 10 + t];
        logits[t] = s;
    }
    __syncthreads();

    if (t == 0) {
        float mx = -1e30f;
        for (int j = 0; j < 10; j++) mx = fmaxf(mx, logits[j]);
        float e[10], sum = 0.0f;
        for (int j = 0; j < 10; j++) { e[j] = expf(logits[j] - mx); sum += e[j]; }
        float inv = 1.0f / sum;
        for (int j = 0; j < 10; j++) out[j] = e[j] * inv;
        for (int j = 0; j < 68; j++) out[10 + j] = code[j];
    }
}

// ---------------- launch ----------------------------------------------------
extern "C" void kernel_launch(void* const* d_in, const int* in_sizes, int n_in,
                              void* d_out, int out_size) {
    const float* x    = (const float*)d_in[0];
    const int*   ei   = (const int*)d_in[1];
    const float* ew   = (const float*)d_in[2];
    const float* C2ER = (const float*)d_in[4];
    const float* W1 = (const float*)d_in[5],  *b1 = (const float*)d_in[6];
    const float* W2 = (const float*)d_in[7],  *b2 = (const float*)d_in[8];
    const float* W3 = (const float*)d_in[9],  *b3 = (const float*)d_in[10];
    const float* W4 = (const float*)d_in[11], *b4 = (const float*)d_in[12];
    const float* L1W = (const float*)d_in[13], *L1b = (const float*)d_in[14];
    const float* L2W = (const float*)d_in[15], *L2b = (const float*)d_in[16];
    const float* L3W = (const float*)d_in[17], *L3b = (const float*)d_in[18];
    float* out = (float*)d_out;

    const int* src = ei;
    const int* dst = ei + NE;

    void *pH, *pA, *pB, *px0, *px1;
    cudaGetSymbolAddress(&pH, g_bufH);
    cudaGetSymbolAddress(&pA, g_bufA);
    cudaGetSymbolAddress(&pB, g_bufB);
    cudaGetSymbolAddress(&px0, g_x0);
    cudaGetSymbolAddress(&px1, g_x1);
    float* H = (float*)pH;
    float* A = (float*)pA;
    float* B = (float*)pB;

    // smem sizes
    const int SM_G1 = (8 * 32 + 64 * 8) * 4;        //  3 KB
    const int SM_G2 = (32 * 128 + 64 * 32) * 4;     // 24 KB
    const int SM_G3 = (128 * 128 + 64 * 128) * 4;   // 96 KB
    const int SM_G4 = (128 * 32 + 64 * 128) * 4;    // 48 KB
    cudaFuncSetAttribute(k_gemm<128, 128, true,  true>,
                         cudaFuncAttributeMaxDynamicSharedMemorySize, SM_G3);
    cudaFuncSetAttribute(k_gemm<128, 32, false, false>,
                         cudaFuncAttributeMaxDynamicSharedMemorySize, SM_G4);

    // ---- CSR build + normalization ----
    k_init  <<<(NN + 255) / 256, 256>>>();
    k_deg   <<<(NE + 255) / 256, 256>>>(dst, ew);
    k_scan1 <<<NBLK, 512>>>();
    k_scan2 <<<1, 256>>>();
    k_scan3 <<<NBLK, 512>>>();
    k_fill  <<<(NE + 255) / 256, 256>>>(src, dst, ew);

    // ---- Layer 1: agg(x)[8] -> GEMM 8->32 (+b1, relu) -> A = h1 ----
    k_agg<8, false><<<(NN * 2 + 255) / 256, 256>>>(x, nullptr, H);
    k_gemm<8, 32, true, true><<<592, 256, SM_G1>>>(H, W1, b1, A);
    k_segmax32<<<448, 256>>>(A, (unsigned*)px0);

    // ---- Layer 2: agg(h1)[32] -> GEMM 32->128 (+b2, relu) -> B = h2 ----
    k_agg<32, false><<<(NN * 8 + 255) / 256, 256>>>(A, nullptr, H);
    k_gemm<32, 128, true, true><<<592, 256, SM_G2>>>(H, W2, b2, B);

    // ---- Layer 3: agg(h2)[128] -> GEMM 128->128 (+b3, relu) -> A = h3 ----
    k_agg<128, false><<<(NN * 32 + 255) / 256, 256>>>(B, nullptr, H);
    k_gemm<128, 128, true, true><<<296, 256, SM_G3>>>(H, W3, b3, A);

    // ---- Layer 4: GEMM 128->32 (no bias) -> agg[32] (+b4) -> B ----
    k_gemm<128, 32, false, false><<<592, 256, SM_G4>>>(A, W4, nullptr, H);
    k_agg<32, true><<<(NN * 8 + 255) / 256, 256>>>(H, b4, B);
    k_segmax32<<<448, 256>>>(B, (unsigned*)px1);

    // ---- Head ----
    k_head<<<1, 128>>>(C2ER, (const unsigned*)px0, (const unsigned*)px1,
                       L1W, L1b, L2W, L2b, L3W, L3b, out);
}

// round 5
// speedup vs baseline: 4.0327x; 1.2399x over previous
#include <cuda_runtime.h>
#include <cuda_bf16.h>
#include <cstdint>

#define NN 100000
#define NE 600000
#define NBLK 196   // ceil(NN/512) scan blocks

// ---------------- scratch (device globals; no allocation allowed) ----------
__device__ float    g_bufH[(size_t)NN * 128];
__device__ float    g_bufA[(size_t)NN * 128];
__device__ float    g_bufB[(size_t)NN * 128];
__device__ float    g_dinv[NN];
__device__ int      g_cnt[NN];
__device__ int      g_loc[NN];
__device__ int      g_bsum[NBLK];
__device__ int      g_rowptr[NN + 1];
__device__ int      g_cur[NN];
__device__ int2     g_edge[NE];
__device__ unsigned g_x0[32];
__device__ unsigned g_x1[32];
__device__ __align__(16) __nv_bfloat16 g_wHi[128 * 128];
__device__ __align__(16) __nv_bfloat16 g_wLo[128 * 128];

// ======================= mma.sync helpers ===================================
__device__ __forceinline__ uint32_t smem_u32(const void* p) {
    uint32_t a;
    asm("{ .reg .u64 t; cvta.to.shared.u64 t, %1; cvt.u32.u64 %0, t; }"
        : "=r"(a) : "l"(p));
    return a;
}

__device__ __forceinline__ void ldmx2(uint32_t* r, uint32_t addr) {
    asm volatile("ldmatrix.sync.aligned.m8n8.x2.shared.b16 {%0,%1}, [%2];"
                 : "=r"(r[0]), "=r"(r[1]) : "r"(addr));
}

__device__ __forceinline__ void mma16816(float* c, const uint32_t* a, const uint32_t* b) {
    asm volatile(
        "mma.sync.aligned.m16n8k16.row.col.f32.bf16.bf16.f32 "
        "{%0,%1,%2,%3}, {%4,%5,%6,%7}, {%8,%9}, {%0,%1,%2,%3};"
        : "+f"(c[0]), "+f"(c[1]), "+f"(c[2]), "+f"(c[3])
        : "r"(a[0]), "r"(a[1]), "r"(a[2]), "r"(a[3]), "r"(b[0]), "r"(b[1]));
}

// float2 -> packed bf16x2 hi + lo residual
__device__ __forceinline__ void cvt2(float2 f, uint32_t& hi, uint32_t& lo) {
    __nv_bfloat162 h = __floats2bfloat162_rn(f.x, f.y);
    float2 hf = __bfloat1622float2(h);
    __nv_bfloat162 l = __floats2bfloat162_rn(f.x - hf.x, f.y - hf.y);
    hi = *(uint32_t*)&h;
    lo = *(uint32_t*)&l;
}

__device__ __forceinline__ void cvt_hilo(float x, unsigned short& h, unsigned short& l) {
    __nv_bfloat16 hb = __float2bfloat16(x);
    __nv_bfloat16 lb = __float2bfloat16(x - __bfloat162float(hb));
    h = __bfloat16_as_ushort(hb);
    l = __bfloat16_as_ushort(lb);
}

// ---------------- weight convert: W[K,N] f32 -> W^T hi/lo bf16 [N,K] --------
template <int K, int N>
__global__ void k_wconv(const float* __restrict__ W) {
    int i = blockIdx.x * 256 + threadIdx.x;
    if (i < N * K) {
        int n = i / K, k = i % K;
        float w = W[k * N + n];
        unsigned short h, l;
        cvt_hilo(w, h, l);
        g_wHi[i] = __ushort_as_bfloat16(h);
        g_wLo[i] = __ushort_as_bfloat16(l);
    }
}

// ---------------- tensor-core GEMM: Hout = [relu](X @ W [+ b]) --------------
// bf16 hi/lo 3-pass (hi*hi + hi*lo + lo*hi) via mma.sync m16n8k16.
// Block = 256 threads = 8 warps; tile = 128 rows (16 rows / warp).
template <int K, int N, bool BIAS, bool RELU>
__global__ void __launch_bounds__(256) k_mma(const float* __restrict__ X,
                                             const float* __restrict__ bias,
                                             float* __restrict__ Hout) {
    constexpr int SK  = K + 8;          // padded bf16 stride (conflict-free)
    constexpr int NT  = N / 8;          // n-tiles per warp
    constexpr int NKC = K / 16;         // k-chunks
    extern __shared__ __nv_bfloat16 sb[];
    __nv_bfloat16* sHi = sb;            // [N][SK]
    __nv_bfloat16* sLo = sb + N * SK;

    int tid = threadIdx.x, wid = tid >> 5, lane = tid & 31;

    // stage W^T hi/lo into padded smem
    for (int i = tid; i < N * (K / 2); i += 256) {
        int n = i / (K / 2), k = (i % (K / 2)) * 2;
        uint32_t h = ((const uint32_t*)g_wHi)[(n * K + k) >> 1];
        uint32_t l = ((const uint32_t*)g_wLo)[(n * K + k) >> 1];
        *(uint32_t*)&sHi[n * SK + k] = h;
        *(uint32_t*)&sLo[n * SK + k] = l;
    }
    __syncthreads();

    int grp = lane >> 2;                // 0..7
    int qk  = (lane & 3) * 2;           // 0,2,4,6
    // ldmatrix.x2 per-lane row address: lanes 0-7 -> rows (k 0..7),
    // lanes 8-15 -> rows (k 8..15); lanes 16-31 replicate.
    int l8   = lane & 7;
    int koff = ((lane >> 3) & 1) * 8;
    uint32_t bHiBase = smem_u32(sHi) + (uint32_t)((l8 * SK + koff) * 2);
    uint32_t bLoBase = smem_u32(sLo) + (uint32_t)((l8 * SK + koff) * 2);

    constexpr int NTILES = (NN + 127) / 128;
    for (int t = blockIdx.x; t < NTILES; t += gridDim.x) {
        int rbase = t * 128 + wid * 16;
        int r0 = rbase + grp;
        int r8 = r0 + 8;
        const float* x0 = X + (size_t)(r0 < NN ? r0 : NN - 1) * K;
        const float* x8 = X + (size_t)(r8 < NN ? r8 : NN - 1) * K;

        float acc[NT][4];
#pragma unroll
        for (int nt = 0; nt < NT; nt++)
#pragma unroll
            for (int j = 0; j < 4; j++) acc[nt][j] = 0.0f;

#pragma unroll
        for (int kc = 0; kc < NKC; kc++) {
            int k = kc * 16 + qk;
            float2 f0 = *(const float2*)(x0 + k);
            float2 f1 = *(const float2*)(x8 + k);
            float2 f2 = *(const float2*)(x0 + k + 8);
            float2 f3 = *(const float2*)(x8 + k + 8);
            uint32_t aHi[4], aLo[4];
            cvt2(f0, aHi[0], aLo[0]);
            cvt2(f1, aHi[1], aLo[1]);
            cvt2(f2, aHi[2], aLo[2]);
            cvt2(f3, aHi[3], aLo[3]);

#pragma unroll
            for (int nt = 0; nt < NT; nt++) {
                uint32_t off = (uint32_t)(nt * 8 * SK * 2 + kc * 32);
                uint32_t bHi[2], bLo[2];
                ldmx2(bHi, bHiBase + off);
                ldmx2(bLo, bLoBase + off);
                mma16816(acc[nt], aHi, bHi);   // hi*hi
                mma16816(acc[nt], aHi, bLo);   // hi*lo
                mma16816(acc[nt], aLo, bHi);   // lo*hi
            }
        }

        bool ok0 = r0 < NN, ok8 = r8 < NN;
#pragma unroll
        for (int nt = 0; nt < NT; nt++) {
            int col = nt * 8 + qk;
            float2 v0 = make_float2(acc[nt][0], acc[nt][1]);
            float2 v1 = make_float2(acc[nt][2], acc[nt][3]);
            if (BIAS) {
                float2 bv = *(const float2*)(bias + col);
                v0.x += bv.x; v0.y += bv.y;
                v1.x += bv.x; v1.y += bv.y;
            }
            if (RELU) {
                v0.x = fmaxf(v0.x, 0.f); v0.y = fmaxf(v0.y, 0.f);
                v1.x = fmaxf(v1.x, 0.f); v1.y = fmaxf(v1.y, 0.f);
            }
            if (ok0) *(float2*)(Hout + (size_t)r0 * N + col) = v0;
            if (ok8) *(float2*)(Hout + (size_t)r8 * N + col) = v1;
        }
    }
}

constexpr int mma_smem(int K, int N) { return 2 * N * (K + 8) * 2; }

// ================== CSR build / agg / small kernels =========================
__global__ void k_init() {
    int i = blockIdx.x * blockDim.x + threadIdx.x;
    if (i < NN) { g_dinv[i] = 1.0f; g_cnt[i] = 0; }
    if (i < 32) { g_x0[i] = 0u; g_x1[i] = 0u; }
}

__global__ void k_deg(const int* __restrict__ dst, const float* __restrict__ ew) {
    int e = blockIdx.x * blockDim.x + threadIdx.x;
    if (e < NE) {
        int d = dst[e];
        atomicAdd(&g_dinv[d], ew[e]);
        atomicAdd(&g_cnt[d], 1);
    }
}

__global__ void k_scan1() {
    __shared__ int s[512];
    int tid = threadIdx.x;
    int i = blockIdx.x * 512 + tid;
    int v = (i < NN) ? g_cnt[i] : 0;
    if (i < NN) g_dinv[i] = rsqrtf(g_dinv[i]);
    s[tid] = v;
    __syncthreads();
#pragma unroll
    for (int off = 1; off < 512; off <<= 1) {
        int t = 0;
        if (tid >= off) t = s[tid - off];
        __syncthreads();
        if (tid >= off) s[tid] += t;
        __syncthreads();
    }
    if (i < NN) g_loc[i] = s[tid] - v;
    if (tid == 511) g_bsum[blockIdx.x] = s[511];
}

__global__ void k_scan2() {
    __shared__ int s[256];
    int t = threadIdx.x;
    int v = (t < NBLK) ? g_bsum[t] : 0;
    s[t] = v;
    __syncthreads();
#pragma unroll
    for (int off = 1; off < 256; off <<= 1) {
        int u = 0;
        if (t >= off) u = s[t - off];
        __syncthreads();
        if (t >= off) s[t] += u;
        __syncthreads();
    }
    if (t < NBLK) g_bsum[t] = s[t] - v;
    if (t == 0) g_rowptr[NN] = NE;
}

__global__ void k_scan3() {
    int i = blockIdx.x * 512 + threadIdx.x;
    if (i < NN) {
        int r = g_loc[i] + g_bsum[blockIdx.x];
        g_rowptr[i] = r;
        g_cur[i] = r;
    }
}

__global__ void k_fill(const int* __restrict__ src, const int* __restrict__ dst,
                       const float* __restrict__ ew) {
    int e = blockIdx.x * blockDim.x + threadIdx.x;
    if (e < NE) {
        int s = src[e], d = dst[e];
        float n = g_dinv[s] * ew[e] * g_dinv[d];
        int pos = atomicAdd(&g_cur[d], 1);
        g_edge[pos] = make_int2(s, __float_as_int(n));
    }
}

template <int WID, bool BIAS>
__global__ void k_agg(const float* __restrict__ h, const float* __restrict__ b,
                      float* __restrict__ out) {
    constexpr int G = WID / 4;
    int idx = blockIdx.x * 256 + threadIdx.x;
    int node = idx / G, g = idx % G;
    if (node >= NN) return;

    int beg = g_rowptr[node];
    int end = g_rowptr[node + 1];
    float d = g_dinv[node]; d = d * d;

    const float4* h4 = (const float4*)h;
    float4 hv = h4[(size_t)node * G + g];
    float4 acc;
    if (BIAS) {
        float4 bv = ((const float4*)b)[g];
        acc.x = hv.x * d + bv.x; acc.y = hv.y * d + bv.y;
        acc.z = hv.z * d + bv.z; acc.w = hv.w * d + bv.w;
    } else {
        acc.x = hv.x * d; acc.y = hv.y * d;
        acc.z = hv.z * d; acc.w = hv.w * d;
    }

    for (int e = beg; e < end; e++) {
        int2 ed = g_edge[e];
        float n = __int_as_float(ed.y);
        float4 v = h4[(size_t)ed.x * G + g];
        acc.x += n * v.x; acc.y += n * v.y;
        acc.z += n * v.z; acc.w += n * v.w;
    }
    ((float4*)out)[(size_t)node * G + g] = acc;
}

// FFMA GEMM kept for tiny layer 1 (8 -> 32)
template <int IN, int OUT, bool BIAS, bool RELU>
__global__ void __launch_bounds__(256) k_gemm(const float* __restrict__ X,
                                              const float* __restrict__ W,
                                              const float* __restrict__ b,
                                              float* __restrict__ H) {
    constexpr int K4 = IN / 4;
    constexpr int ROWS = 64;
    extern __shared__ float sm[];
    float* sW = sm;
    float* sX = sm + IN * OUT;
    int tid = threadIdx.x;
    int tx = tid & 31, ty = tid >> 5;

    for (int i = tid; i < IN * OUT / 4; i += 256)
        ((float4*)sW)[i] = ((const float4*)W)[i];

    float bv = 0.0f;
    if (BIAS) bv = b[tx];
    __syncthreads();

    const int ntiles = (NN + ROWS - 1) / ROWS;
    for (int t = blockIdx.x; t < ntiles; t += gridDim.x) {
        int rbase = t * ROWS;
        for (int i = tid; i < ROWS * K4; i += 256) {
            int r = i / K4;
            float4 v = make_float4(0.f, 0.f, 0.f, 0.f);
            if (rbase + r < NN) v = ((const float4*)X)[(size_t)(rbase + r) * K4 + (i % K4)];
            ((float4*)sX)[i] = v;
        }
        __syncthreads();

        float acc[8];
#pragma unroll
        for (int rr = 0; rr < 8; rr++) acc[rr] = 0.0f;

#pragma unroll
        for (int k4 = 0; k4 < K4; k4++) {
            float4 xr[8];
#pragma unroll
            for (int rr = 0; rr < 8; rr++)
                xr[rr] = ((float4*)sX)[(ty * 8 + rr) * K4 + k4];
#pragma unroll
            for (int kk = 0; kk < 4; kk++) {
                float wv = sW[(k4 * 4 + kk) * 32 + tx];
#pragma unroll
                for (int rr = 0; rr < 8; rr++)
                    acc[rr] += ((const float*)&xr[rr])[kk] * wv;
            }
        }

#pragma unroll
        for (int rr = 0; rr < 8; rr++) {
            int row = rbase + ty * 8 + rr;
            if (row < NN) {
                float v = acc[rr];
                if (BIAS) v += bv;
                if (RELU) v = fmaxf(v, 0.0f);
                H[(size_t)row * 32 + tx] = v;
            }
        }
        __syncthreads();
    }
}

__global__ void k_segmax32(const float* __restrict__ buf, unsigned* __restrict__ out) {
    int f = threadIdx.x & 31;
    int w = threadIdx.x >> 5;
    float m = 0.0f;
    for (int i = blockIdx.x * 8 + w; i < NN; i += gridDim.x * 8)
        m = fmaxf(m, buf[(size_t)i * 32 + f]);
    __shared__ float s[256];
    s[threadIdx.x] = m;
    __syncthreads();
    if (threadIdx.x < 32) {
#pragma unroll
        for (int ww = 1; ww < 8; ww++) m = fmaxf(m, s[ww * 32 + f]);
        atomicMax(&out[f], __float_as_uint(m));
    }
}

__global__ void k_head(const float* __restrict__ C2ER,
                       const unsigned* __restrict__ x0, const unsigned* __restrict__ x1,
                       const float* __restrict__ L1W, const float* __restrict__ L1b,
                       const float* __restrict__ L2W, const float* __restrict__ L2b,
                       const float* __restrict__ L3W, const float* __restrict__ L3b,
                       float* __restrict__ out) {
    __shared__ float code[68], z1[128], z2[128], logits[10];
    int t = threadIdx.x;
    if (t < 32)       code[t] = __uint_as_float(x0[t]);
    else if (t < 64)  code[t] = __uint_as_float(x1[t - 32]);
    else if (t < 68)  code[t] = C2ER[t - 64];
    __syncthreads();

    float a = L1b[t];
#pragma unroll
    for (int i = 0; i < 68; i++) a += code[i] * L1W[i * 128 + t];
    z1[t] = fmaxf(a, 0.0f);
    __syncthreads();

    a = L2b[t];
#pragma unroll
    for (int i = 0; i < 128; i++) a += z1[i] * L2W[i * 128 + t];
    z2[t] = fmaxf(a, 0.0f);
    __syncthreads();

    if (t < 10) {
        float s = L3b[t];
#pragma unroll
        for (int i = 0; i < 128; i++) s += z2[i] * L3W[i * 10 + t];
        logits[t] = s;
    }
    __syncthreads();

    if (t == 0) {
        float mx = -1e30f;
        for (int j = 0; j < 10; j++) mx = fmaxf(mx, logits[j]);
        float e[10], sum = 0.0f;
        for (int j = 0; j < 10; j++) { e[j] = expf(logits[j] - mx); sum += e[j]; }
        float inv = 1.0f / sum;
        for (int j = 0; j < 10; j++) out[j] = e[j] * inv;
        for (int j = 0; j < 68; j++) out[10 + j] = code[j];
    }
}

// ---------------- launch ----------------------------------------------------
extern "C" void kernel_launch(void* const* d_in, const int* in_sizes, int n_in,
                              void* d_out, int out_size) {
    const float* x    = (const float*)d_in[0];
    const int*   ei   = (const int*)d_in[1];
    const float* ew   = (const float*)d_in[2];
    const float* C2ER = (const float*)d_in[4];
    const float* W1 = (const float*)d_in[5],  *b1 = (const float*)d_in[6];
    const float* W2 = (const float*)d_in[7],  *b2 = (const float*)d_in[8];
    const float* W3 = (const float*)d_in[9],  *b3 = (const float*)d_in[10];
    const float* W4 = (const float*)d_in[11], *b4 = (const float*)d_in[12];
    const float* L1W = (const float*)d_in[13], *L1b = (const float*)d_in[14];
    const float* L2W = (const float*)d_in[15], *L2b = (const float*)d_in[16];
    const float* L3W = (const float*)d_in[17], *L3b = (const float*)d_in[18];
    float* out = (float*)d_out;

    const int* src = ei;
    const int* dst = ei + NE;

    void *pH, *pA, *pB, *px0, *px1;
    cudaGetSymbolAddress(&pH, g_bufH);
    cudaGetSymbolAddress(&pA, g_bufA);
    cudaGetSymbolAddress(&pB, g_bufB);
    cudaGetSymbolAddress(&px0, g_x0);
    cudaGetSymbolAddress(&px1, g_x1);
    float* H = (float*)pH;
    float* A = (float*)pA;
    float* B = (float*)pB;

    const int SM_G1 = (8 * 32 + 64 * 8) * 4;
    constexpr int SM_M2 = mma_smem(32, 128);    // 20,480 B
    constexpr int SM_M3 = mma_smem(128, 128);   // 69,632 B
    constexpr int SM_M4 = mma_smem(128, 32);    // 17,408 B
    cudaFuncSetAttribute(k_mma<128, 128, true, true>,
                         cudaFuncAttributeMaxDynamicSharedMemorySize, SM_M3);

    // ---- CSR build + normalization ----
    k_init  <<<(NN + 255) / 256, 256>>>();
    k_deg   <<<(NE + 255) / 256, 256>>>(dst, ew);
    k_scan1 <<<NBLK, 512>>>();
    k_scan2 <<<1, 256>>>();
    k_scan3 <<<NBLK, 512>>>();
    k_fill  <<<(NE + 255) / 256, 256>>>(src, dst, ew);

    // ---- Layer 1: agg(x)[8] -> FFMA GEMM 8->32 (+b1, relu) -> A ----
    k_agg<8, false><<<(NN * 2 + 255) / 256, 256>>>(x, nullptr, H);
    k_gemm<8, 32, true, true><<<592, 256, SM_G1>>>(H, W1, b1, A);
    k_segmax32<<<448, 256>>>(A, (unsigned*)px0);

    // ---- Layer 2: agg(h1)[32] -> MMA 32->128 (+b2, relu) -> B ----
    k_agg<32, false><<<(NN * 8 + 255) / 256, 256>>>(A, nullptr, H);
    k_wconv<32, 128><<<(32 * 128 + 255) / 256, 256>>>(W2);
    k_mma<32, 128, true, true><<<391, 256, SM_M2>>>(H, b2, B);

    // ---- Layer 3: agg(h2)[128] -> MMA 128->128 (+b3, relu) -> A ----
    k_agg<128, false><<<(NN * 32 + 255) / 256, 256>>>(B, nullptr, H);
    k_wconv<128, 128><<<(128 * 128 + 255) / 256, 256>>>(W3);
    k_mma<128, 128, true, true><<<296, 256, SM_M3>>>(H, b3, A);

    // ---- Layer 4: MMA 128->32 -> agg[32] (+b4) -> B ----
    k_wconv<128, 32><<<(128 * 32 + 255) / 256, 256>>>(W4);
    k_mma<128, 32, false, false><<<391, 256, SM_M4>>>(A, nullptr, H);
    k_agg<32, true><<<(NN * 8 + 255) / 256, 256>>>(H, b4, B);
    k_segmax32<<<448, 256>>>(B, (unsigned*)px1);

    // ---- Head ----
    k_head<<<1, 128>>>(C2ER, (const unsigned*)px0, (const unsigned*)px1,
                       L1W, L1b, L2W, L2b, L3W, L3b, out);
}